// round 5
// baseline (speedup 1.0000x reference)
#include <cuda_runtime.h>
#include <cuda_fp16.h>
#include <cstdint>

#define HIDDEN 1024
#define EMBD   512
#define KAUG   1536
#define NOPS   8
#define BATCH  16384

#define BM 128
#define BN 128
#define BKH 64                      /* halves per k-chunk = 128B rows */
#define STAGE_BYTES 32768           /* A 16KB + B 16KB */
#define OFF_TOK  (2 * STAGE_BYTES)
#define OFF_BIAS (OFF_TOK + 512)
#define SMEM_TOTAL (OFF_BIAS + 512)

// ---------------- device scratch ----------------
__device__ int    g_counts[NOPS];
__device__ int    g_bucket[NOPS][BATCH];
__device__ __half g_Xh[(size_t)BATCH * HIDDEN];            // fp16(x), k-permuted
__device__ __half g_Eh[NOPS * EMBD];                       // fp16(emb), k-permuted
__device__ __half g_Hh[(size_t)BATCH * HIDDEN];            // fp16(H), k-permuted
__device__ __half g_WTh1[(size_t)NOPS * HIDDEN * KAUG];    // [e][n][perm k]
__device__ __half g_WTh2[(size_t)NOPS * HIDDEN * HIDDEN];  // [e][n][perm k]

// ---------------- helpers ----------------
__device__ __forceinline__ uint32_t smem_u32(const void* p) {
    uint32_t a;
    asm("{ .reg .u64 t; cvta.to.shared.u64 t, %1; cvt.u32.u64 %0, t; }" : "=r"(a) : "l"(p));
    return a;
}
__device__ __forceinline__ void cp16(uint32_t dst, const void* src) {
    asm volatile("cp.async.cg.shared.global [%0], [%1], 16;" :: "r"(dst), "l"(src));
}
#define CP_COMMIT() asm volatile("cp.async.commit_group;" ::: "memory")
#define CP_WAIT1()  asm volatile("cp.async.wait_group 1;" ::: "memory")

__device__ __forceinline__ void mma_f16(
    float& c0, float& c1, float& c2, float& c3,
    uint32_t a0, uint32_t a1, uint32_t a2, uint32_t a3,
    uint32_t b0, uint32_t b1)
{
    asm volatile(
        "mma.sync.aligned.m16n8k16.row.col.f32.f16.f16.f32 "
        "{%0,%1,%2,%3}, {%4,%5,%6,%7}, {%8,%9}, {%0,%1,%2,%3};"
        : "+f"(c0), "+f"(c1), "+f"(c2), "+f"(c3)
        : "r"(a0), "r"(a1), "r"(a2), "r"(a3), "r"(b0), "r"(b1));
}

// k-permute within each 64-half block:
// step s=(k>>4)&3, pair p=(k>>1)&7 -> 16B unit u = (s>>1)*4 + (p&3),
// slot j = (s&1)*2 + (p>>2).  Half index of even k within block:
__device__ __forceinline__ int hperm(int k) {   // k even
    const int s = (k >> 4) & 3, p = (k >> 1) & 7;
    return (k & ~63) + (s >> 1) * 32 + (p & 3) * 8 + (s & 1) * 4 + (p >> 2) * 2;
}

// ---------------- routing ----------------
__global__ void zero_counts_kernel() {
    if (threadIdx.x < NOPS) g_counts[threadIdx.x] = 0;
}
__global__ void route_kernel(const int* __restrict__ ops) {
    int t = blockIdx.x * blockDim.x + threadIdx.x;
    if (t < BATCH) {
        int e = ops[t];
        int slot = atomicAdd(&g_counts[e], 1);
        g_bucket[e][slot] = t;
    }
}

// ---------------- cvt float -> fp16, k-permuted (x, emb) ----------------
// thread t produces one 16B output unit (8 halves) of block t>>3, unit u=t&7
__global__ void cvt_perm_h_kernel(const float* __restrict__ in, __half* __restrict__ out,
                                  int nunits) {
    int t = blockIdx.x * blockDim.x + threadIdx.x;
    if (t >= nunits) return;
    const int blk = t >> 3, u = t & 7;
    const float* src = in + blk * 64;
    __half h[8];
    #pragma unroll
    for (int j = 0; j < 4; j++) {
        const int s = (u >> 2) * 2 + (j >> 1);
        const int p = (u & 3) + (j & 1) * 4;
        const int k = s * 16 + p * 2;
        h[j * 2 + 0] = __float2half_rn(src[k]);
        h[j * 2 + 1] = __float2half_rn(src[k + 1]);
    }
    ((uint4*)out)[t] = *(const uint4*)h;
}

// ---------------- W transpose + fp16 + k-permute: WT[e][n][perm k] = h(W[e][k][n]) ----------------
__global__ void transpose_h_kernel(const float* __restrict__ W, __half* __restrict__ WT,
                                   int K, int N) {
    __shared__ float t[32][33];
    const int e = blockIdx.z;
    const float* Wb = W + (size_t)e * K * N;
    __half* WTb = WT + (size_t)e * N * K;
    const int k0 = blockIdx.y * 32, n0 = blockIdx.x * 32;
    const int x = threadIdx.x, y = threadIdx.y;   // (32, 8)
    #pragma unroll
    for (int r = 0; r < 4; r++)
        t[y + 8 * r][x] = Wb[(size_t)(k0 + y + 8 * r) * N + n0 + x];
    __syncthreads();
    const int tid = y * 32 + x;
    if (tid < 128) {
        const int n_l = tid >> 2, u2 = tid & 3;
        const int u_abs = ((k0 >> 5) & 1) * 4 + u2;
        __half h[8];
        #pragma unroll
        for (int j = 0; j < 4; j++) {
            const int s = (u_abs >> 2) * 2 + (j >> 1);
            const int p = (u_abs & 3) + (j & 1) * 4;
            const int kl = ((s & 1) * 16 + p * 2);           // k within this 32-tile
            h[j * 2 + 0] = __float2half_rn(t[kl][n_l]);
            h[j * 2 + 1] = __float2half_rn(t[kl + 1][n_l]);
        }
        *(uint4*)&WTb[(size_t)(n0 + n_l) * K + (k0 & ~63) + u_abs * 8] = *(const uint4*)h;
    }
}

// ---------------- grouped fp16 GEMM via mma.sync m16n8k16 ----------------
// out[tok, n0:n0+128] = relu( A[tok] @ WT[e]^T + b[e] )
// CTA 128x128x64h, 4 warps of 64x64, 2-stage cp.async, 3 CTAs/SM
template<int KTOT, bool IS_L1>
__global__ void __launch_bounds__(128, 3) moe_gemm_h(
    const __half* __restrict__ WT,
    const float* __restrict__ bias,
    float* __restrict__ outp)
{
    const int e = blockIdx.z;
    const int count = g_counts[e];
    const int m0 = blockIdx.y * BM;
    if (m0 >= count) return;
    const int n0 = blockIdx.x * BN;

    extern __shared__ char smem[];
    const uint32_t sb = smem_u32(smem);
    const int tid = threadIdx.x;
    const int wid = tid >> 5, lane = tid & 31;
    const int g = lane >> 2, t4 = lane & 3;
    const int wm = wid >> 1, wn = wid & 1;

    int*   sTok  = (int*)(smem + OFF_TOK);
    float* sBias = (float*)(smem + OFF_BIAS);
    {
        int idx = m0 + tid;
        sTok[tid]  = g_bucket[e][idx < count ? idx : count - 1];
        sBias[tid] = bias[e * HIDDEN + n0 + tid];
    }
    __syncthreads();

    const __half* __restrict__ Asrc = IS_L1 ? (const __half*)g_Xh : (const __half*)g_Hh;
    const __half* __restrict__ WTe  = WT + (size_t)e * HIDDEN * KTOT;
    const __half* __restrict__ Eh   = g_Eh + e * EMBD;

    // loader: unit lu = tid&7, rows (tid>>3) + 16*i ; swizzle unit ^= (row&1)<<2
    const int lu = tid & 7;
    const int lr0 = tid >> 3;
    const uint32_t lsw = (uint32_t)(lu ^ ((lr0 & 1) << 2)) << 4;

    auto load_chunk = [&](int chunk, int buf) {
        const int k0h = chunk * BKH;
        const uint32_t Abu = sb + buf * STAGE_BYTES;
        const uint32_t Bbu = Abu + 16384;
        #pragma unroll
        for (int i = 0; i < 8; i++) {
            const int r = lr0 + i * 16;
            const __half* asrc;
            if (IS_L1 && k0h >= HIDDEN)
                asrc = Eh + (k0h - HIDDEN);
            else
                asrc = Asrc + (size_t)sTok[r] * HIDDEN + k0h;
            cp16(Abu + r * 128 + lsw, asrc + lu * 8);
            cp16(Bbu + r * 128 + lsw, WTe + (size_t)(n0 + r) * KTOT + k0h + lu * 8);
        }
    };

    float c[4][8][4];
    #pragma unroll
    for (int im = 0; im < 4; im++)
        #pragma unroll
        for (int in_ = 0; in_ < 8; in_++)
            #pragma unroll
            for (int j = 0; j < 4; j++) c[im][in_][j] = 0.0f;

    constexpr int NC = KTOT / BKH;

    load_chunk(0, 0); CP_COMMIT();

    for (int i = 0; i < NC; i++) {
        if (i + 1 < NC) load_chunk(i + 1, (i + 1) & 1);
        CP_COMMIT();
        CP_WAIT1();
        __syncthreads();

        const char* Ab = smem + (i & 1) * STAGE_BYTES;
        const char* Bb = Ab + 16384;

        #pragma unroll
        for (int kb = 0; kb < 2; kb++) {
            uint4 av0[4], av8[4], bv[8];
            #pragma unroll
            for (int im = 0; im < 4; im++) {
                const int r0 = wm * 64 + im * 16 + g;
                const int r8 = r0 + 8;
                av0[im] = *(const uint4*)(Ab + r0 * 128 + (((kb ^ (r0 & 1)) * 4 + t4) << 4));
                av8[im] = *(const uint4*)(Ab + r8 * 128 + (((kb ^ (r8 & 1)) * 4 + t4) << 4));
            }
            #pragma unroll
            for (int in_ = 0; in_ < 8; in_++) {
                const int rb = wn * 64 + in_ * 8 + g;
                bv[in_] = *(const uint4*)(Bb + rb * 128 + (((kb ^ (rb & 1)) * 4 + t4) << 4));
            }
            // s2=0: halves .x/.y (k16 step 2kb) ; s2=1: .z/.w (step 2kb+1)
            #pragma unroll
            for (int s2 = 0; s2 < 2; s2++) {
                #pragma unroll
                for (int im = 0; im < 4; im++) {
                    const uint32_t a0 = s2 ? av0[im].z : av0[im].x;
                    const uint32_t a2 = s2 ? av0[im].w : av0[im].y;
                    const uint32_t a1 = s2 ? av8[im].z : av8[im].x;
                    const uint32_t a3 = s2 ? av8[im].w : av8[im].y;
                    #pragma unroll
                    for (int in_ = 0; in_ < 8; in_++) {
                        const uint32_t b0 = s2 ? bv[in_].z : bv[in_].x;
                        const uint32_t b1 = s2 ? bv[in_].w : bv[in_].y;
                        mma_f16(c[im][in_][0], c[im][in_][1], c[im][in_][2], c[im][in_][3],
                                a0, a1, a2, a3, b0, b1);
                    }
                }
            }
        }
        __syncthreads();
    }

    // ---- epilogue: +bias, relu; L1 -> permuted fp16 H; L2 -> float out ----
    #pragma unroll
    for (int im = 0; im < 4; im++) {
        const int r0 = wm * 64 + im * 16 + g;
        const int r8 = r0 + 8;
        const bool v0 = (m0 + r0) < count;
        const bool v8 = (m0 + r8) < count;
        const int tok0 = sTok[r0];
        const int tok8 = sTok[r8];
        #pragma unroll
        for (int in_ = 0; in_ < 8; in_++) {
            const int cb = wn * 64 + in_ * 8 + 2 * t4;   // local col, even
            const float bias0 = sBias[cb], bias1 = sBias[cb + 1];
            float y00 = fmaxf(c[im][in_][0] + bias0, 0.0f);
            float y01 = fmaxf(c[im][in_][1] + bias1, 0.0f);
            float y80 = fmaxf(c[im][in_][2] + bias0, 0.0f);
            float y81 = fmaxf(c[im][in_][3] + bias1, 0.0f);
            if (IS_L1) {
                const int ph = hperm(n0 + cb);
                if (v0) *(__half2*)&g_Hh[(size_t)tok0 * HIDDEN + ph] = __floats2half2_rn(y00, y01);
                if (v8) *(__half2*)&g_Hh[(size_t)tok8 * HIDDEN + ph] = __floats2half2_rn(y80, y81);
            } else {
                if (v0) *(float2*)(outp + (size_t)tok0 * HIDDEN + n0 + cb) = make_float2(y00, y01);
                if (v8) *(float2*)(outp + (size_t)tok8 * HIDDEN + n0 + cb) = make_float2(y80, y81);
            }
        }
    }
}

// ---------------- launch ----------------
extern "C" void kernel_launch(void* const* d_in, const int* in_sizes, int n_in,
                              void* d_out, int out_size) {
    const float* x      = (const float*)d_in[0];
    const int*   ops    = (const int*)  d_in[1];
    const float* op_emb = (const float*)d_in[2];
    const float* W1     = (const float*)d_in[3];
    const float* b1     = (const float*)d_in[4];
    const float* W2     = (const float*)d_in[5];
    const float* b2     = (const float*)d_in[6];
    float* out = (float*)d_out;

    void *xh = nullptr, *eh = nullptr, *wt1 = nullptr, *wt2 = nullptr;
    cudaGetSymbolAddress(&xh,  g_Xh);
    cudaGetSymbolAddress(&eh,  g_Eh);
    cudaGetSymbolAddress(&wt1, g_WTh1);
    cudaGetSymbolAddress(&wt2, g_WTh2);

    cudaFuncSetAttribute(moe_gemm_h<KAUG, true>,
                         cudaFuncAttributeMaxDynamicSharedMemorySize, SMEM_TOTAL);
    cudaFuncSetAttribute(moe_gemm_h<HIDDEN, false>,
                         cudaFuncAttributeMaxDynamicSharedMemorySize, SMEM_TOTAL);

    zero_counts_kernel<<<1, 32>>>();
    route_kernel<<<BATCH / 256, 256>>>(ops);

    cvt_perm_h_kernel<<<(BATCH * HIDDEN / 8) / 256, 256>>>(x, (__half*)xh, BATCH * HIDDEN / 8);
    cvt_perm_h_kernel<<<(NOPS * EMBD / 8 + 255) / 256, 256>>>(op_emb, (__half*)eh, NOPS * EMBD / 8);

    transpose_h_kernel<<<dim3(HIDDEN/32, KAUG/32, NOPS),   dim3(32, 8)>>>(W1, (__half*)wt1, KAUG, HIDDEN);
    transpose_h_kernel<<<dim3(HIDDEN/32, HIDDEN/32, NOPS), dim3(32, 8)>>>(W2, (__half*)wt2, HIDDEN, HIDDEN);

    dim3 grid(HIDDEN / BN, BATCH / BM, NOPS);
    moe_gemm_h<KAUG,   true ><<<grid, 128, SMEM_TOTAL>>>((const __half*)wt1, b1, out);
    moe_gemm_h<HIDDEN, false><<<grid, 128, SMEM_TOTAL>>>((const __half*)wt2, b2, out);
}

// round 6
// speedup vs baseline: 1.9564x; 1.9564x over previous
#include <cuda_runtime.h>
#include <cuda_fp16.h>
#include <cstdint>

#define HIDDEN 1024
#define EMBD   512
#define KAUG   1536
#define NOPS   8
#define BATCH  16384

#define BM 128
#define BN 128
#define BKH 64                      /* halves per k-chunk = 128B rows */
#define STAGES 3
#define STAGE_BYTES 32768           /* A 16KB + B 16KB */
#define OFF_TOK  (STAGES * STAGE_BYTES)
#define OFF_BIAS (OFF_TOK + 512)
#define SMEM_TOTAL (OFF_BIAS + 512)

// ---------------- device scratch ----------------
__device__ int    g_counts[NOPS];
__device__ int    g_bucket[NOPS][BATCH];
__device__ __half g_Xh[(size_t)BATCH * HIDDEN];            // fp16(x), k-permuted
__device__ __half g_Eh[NOPS * EMBD];                       // fp16(emb), k-permuted
__device__ __half g_Hh[(size_t)BATCH * HIDDEN];            // fp16(H), k-permuted
__device__ __half g_WTh1[(size_t)NOPS * HIDDEN * KAUG];    // [e][n][perm k]
__device__ __half g_WTh2[(size_t)NOPS * HIDDEN * HIDDEN];  // [e][n][perm k]

// ---------------- helpers ----------------
__device__ __forceinline__ uint32_t smem_u32(const void* p) {
    uint32_t a;
    asm("{ .reg .u64 t; cvta.to.shared.u64 t, %1; cvt.u32.u64 %0, t; }" : "=r"(a) : "l"(p));
    return a;
}
__device__ __forceinline__ void cp16(uint32_t dst, const void* src) {
    asm volatile("cp.async.cg.shared.global [%0], [%1], 16;" :: "r"(dst), "l"(src));
}
#define CP_COMMIT() asm volatile("cp.async.commit_group;" ::: "memory")
#define CP_WAIT1()  asm volatile("cp.async.wait_group 1;" ::: "memory")

__device__ __forceinline__ void mma_f16(
    float& c0, float& c1, float& c2, float& c3,
    uint32_t a0, uint32_t a1, uint32_t a2, uint32_t a3,
    uint32_t b0, uint32_t b1)
{
    asm volatile(
        "mma.sync.aligned.m16n8k16.row.col.f32.f16.f16.f32 "
        "{%0,%1,%2,%3}, {%4,%5,%6,%7}, {%8,%9}, {%0,%1,%2,%3};"
        : "+f"(c0), "+f"(c1), "+f"(c2), "+f"(c3)
        : "r"(a0), "r"(a1), "r"(a2), "r"(a3), "r"(b0), "r"(b1));
}

// k-permute within each 64-half block (even k): step s=(k>>4)&3, pair p=(k>>1)&7
__device__ __forceinline__ int hperm(int k) {   // k even
    const int s = (k >> 4) & 3, p = (k >> 1) & 7;
    return (k & ~63) + (s >> 1) * 32 + (p & 3) * 8 + (s & 1) * 4 + (p >> 2) * 2;
}

// ---------------- routing ----------------
__global__ void zero_counts_kernel() {
    if (threadIdx.x < NOPS) g_counts[threadIdx.x] = 0;
}
__global__ void route_kernel(const int* __restrict__ ops) {
    int t = blockIdx.x * blockDim.x + threadIdx.x;
    if (t < BATCH) {
        int e = ops[t];
        int slot = atomicAdd(&g_counts[e], 1);
        g_bucket[e][slot] = t;
    }
}

// ---------------- cvt float -> fp16, k-permuted (x, emb) ----------------
__global__ void cvt_perm_h_kernel(const float* __restrict__ in, __half* __restrict__ out,
                                  int nunits) {
    int t = blockIdx.x * blockDim.x + threadIdx.x;
    if (t >= nunits) return;
    const int blk = t >> 3, u = t & 7;
    const float* src = in + blk * 64;
    __half h[8];
    #pragma unroll
    for (int j = 0; j < 4; j++) {
        const int s = (u >> 2) * 2 + (j >> 1);
        const int p = (u & 3) + (j & 1) * 4;
        const int k = s * 16 + p * 2;
        h[j * 2 + 0] = __float2half_rn(src[k]);
        h[j * 2 + 1] = __float2half_rn(src[k + 1]);
    }
    ((uint4*)out)[t] = *(const uint4*)h;
}

// ---------------- W transpose + fp16 + k-permute ----------------
__global__ void transpose_h_kernel(const float* __restrict__ W, __half* __restrict__ WT,
                                   int K, int N) {
    __shared__ float t[32][33];
    const int e = blockIdx.z;
    const float* Wb = W + (size_t)e * K * N;
    __half* WTb = WT + (size_t)e * N * K;
    const int k0 = blockIdx.y * 32, n0 = blockIdx.x * 32;
    const int x = threadIdx.x, y = threadIdx.y;   // (32, 8)
    #pragma unroll
    for (int r = 0; r < 4; r++)
        t[y + 8 * r][x] = Wb[(size_t)(k0 + y + 8 * r) * N + n0 + x];
    __syncthreads();
    const int tid = y * 32 + x;
    if (tid < 128) {
        const int n_l = tid >> 2, u2 = tid & 3;
        const int u_abs = ((k0 >> 5) & 1) * 4 + u2;
        __half h[8];
        #pragma unroll
        for (int j = 0; j < 4; j++) {
            const int s = (u_abs >> 2) * 2 + (j >> 1);
            const int p = (u_abs & 3) + (j & 1) * 4;
            const int kl = ((s & 1) * 16 + p * 2);
            h[j * 2 + 0] = __float2half_rn(t[kl][n_l]);
            h[j * 2 + 1] = __float2half_rn(t[kl + 1][n_l]);
        }
        *(uint4*)&WTb[(size_t)(n0 + n_l) * K + (k0 & ~63) + u_abs * 8] = *(const uint4*)h;
    }
}

// ---------------- grouped fp16 GEMM via mma.sync m16n8k16 ----------------
// CTA 128x128x64h, 256 threads, 8 warps of 64x32, 3-stage cp.async, 2 CTAs/SM
template<int KTOT, bool IS_L1>
__global__ void __launch_bounds__(256, 2) moe_gemm_h(
    const __half* __restrict__ WT,
    const float* __restrict__ bias,
    float* __restrict__ outp)
{
    const int e = blockIdx.z;
    const int count = g_counts[e];
    const int m0 = blockIdx.y * BM;
    if (m0 >= count) return;
    const int n0 = blockIdx.x * BN;

    extern __shared__ char smem[];
    const uint32_t sb = smem_u32(smem);
    const int tid = threadIdx.x;
    const int wid = tid >> 5, lane = tid & 31;
    const int g = lane >> 2, t4 = lane & 3;
    const int wm = wid >> 2, wn = wid & 3;     // 2 (m) x 4 (n) warp grid

    int*   sTok  = (int*)(smem + OFF_TOK);
    float* sBias = (float*)(smem + OFF_BIAS);
    if (tid < 128) {
        int idx = m0 + tid;
        sTok[tid]  = g_bucket[e][idx < count ? idx : count - 1];
        sBias[tid] = bias[e * HIDDEN + n0 + tid];
    }
    __syncthreads();

    const __half* __restrict__ Asrc = IS_L1 ? (const __half*)g_Xh : (const __half*)g_Hh;
    const __half* __restrict__ WTe  = WT + (size_t)e * HIDDEN * KTOT;
    const __half* __restrict__ Eh   = g_Eh + e * EMBD;

    // loader: 256 threads, each 4 A-units + 4 B-units per chunk
    const int lu = tid & 7;                    // 16B unit within 128B row
    const int lr0 = tid >> 3;                  // 0..31
    const uint32_t lsw = (uint32_t)(lu ^ ((lr0 & 1) << 2)) << 4;

    auto load_chunk = [&](int chunk, int buf) {
        const int k0h = chunk * BKH;
        const uint32_t Abu = sb + buf * STAGE_BYTES;
        const uint32_t Bbu = Abu + 16384;
        #pragma unroll
        for (int i = 0; i < 4; i++) {
            const int r = lr0 + i * 32;
            const __half* asrc;
            if (IS_L1 && k0h >= HIDDEN)
                asrc = Eh + (k0h - HIDDEN);
            else
                asrc = Asrc + (size_t)sTok[r] * HIDDEN + k0h;
            cp16(Abu + r * 128 + lsw, asrc + lu * 8);
            cp16(Bbu + r * 128 + lsw, WTe + (size_t)(n0 + r) * KTOT + k0h + lu * 8);
        }
    };

    float c[4][4][4];
    #pragma unroll
    for (int im = 0; im < 4; im++)
        #pragma unroll
        for (int in_ = 0; in_ < 4; in_++)
            #pragma unroll
            for (int j = 0; j < 4; j++) c[im][in_][j] = 0.0f;

    constexpr int NC = KTOT / BKH;

    load_chunk(0, 0); CP_COMMIT();
    load_chunk(1, 1); CP_COMMIT();

    for (int i = 0; i < NC; i++) {
        CP_WAIT1();
        __syncthreads();
        const int nb = i + 2;
        if (nb < NC) load_chunk(nb, nb % STAGES);
        CP_COMMIT();

        const char* Ab = smem + (i % STAGES) * STAGE_BYTES;
        const char* Bb = Ab + 16384;

        #pragma unroll
        for (int kb = 0; kb < 2; kb++) {
            uint4 av0[4], av8[4], bv[4];
            #pragma unroll
            for (int im = 0; im < 4; im++) {
                const int r0 = wm * 64 + im * 16 + g;
                const int r8 = r0 + 8;
                av0[im] = *(const uint4*)(Ab + r0 * 128 + (((kb ^ (r0 & 1)) * 4 + t4) << 4));
                av8[im] = *(const uint4*)(Ab + r8 * 128 + (((kb ^ (r8 & 1)) * 4 + t4) << 4));
            }
            #pragma unroll
            for (int in_ = 0; in_ < 4; in_++) {
                const int rb = wn * 32 + in_ * 8 + g;
                bv[in_] = *(const uint4*)(Bb + rb * 128 + (((kb ^ (rb & 1)) * 4 + t4) << 4));
            }
            #pragma unroll
            for (int s2 = 0; s2 < 2; s2++) {
                #pragma unroll
                for (int im = 0; im < 4; im++) {
                    const uint32_t a0 = s2 ? av0[im].z : av0[im].x;
                    const uint32_t a2 = s2 ? av0[im].w : av0[im].y;
                    const uint32_t a1 = s2 ? av8[im].z : av8[im].x;
                    const uint32_t a3 = s2 ? av8[im].w : av8[im].y;
                    #pragma unroll
                    for (int in_ = 0; in_ < 4; in_++) {
                        const uint32_t b0 = s2 ? bv[in_].z : bv[in_].x;
                        const uint32_t b1 = s2 ? bv[in_].w : bv[in_].y;
                        mma_f16(c[im][in_][0], c[im][in_][1], c[im][in_][2], c[im][in_][3],
                                a0, a1, a2, a3, b0, b1);
                    }
                }
            }
        }
    }

    // ---- epilogue: +bias, relu; L1 -> permuted fp16 H; L2 -> float out ----
    #pragma unroll
    for (int im = 0; im < 4; im++) {
        const int r0 = wm * 64 + im * 16 + g;
        const int r8 = r0 + 8;
        const bool v0 = (m0 + r0) < count;
        const bool v8 = (m0 + r8) < count;
        const int tok0 = sTok[r0];
        const int tok8 = sTok[r8];
        #pragma unroll
        for (int in_ = 0; in_ < 4; in_++) {
            const int cb = wn * 32 + in_ * 8 + 2 * t4;   // local col, even
            const float bias0 = sBias[cb], bias1 = sBias[cb + 1];
            float y00 = fmaxf(c[im][in_][0] + bias0, 0.0f);
            float y01 = fmaxf(c[im][in_][1] + bias1, 0.0f);
            float y80 = fmaxf(c[im][in_][2] + bias0, 0.0f);
            float y81 = fmaxf(c[im][in_][3] + bias1, 0.0f);
            if (IS_L1) {
                const int ph = hperm(n0 + cb);
                if (v0) *(__half2*)&g_Hh[(size_t)tok0 * HIDDEN + ph] = __floats2half2_rn(y00, y01);
                if (v8) *(__half2*)&g_Hh[(size_t)tok8 * HIDDEN + ph] = __floats2half2_rn(y80, y81);
            } else {
                if (v0) *(float2*)(outp + (size_t)tok0 * HIDDEN + n0 + cb) = make_float2(y00, y01);
                if (v8) *(float2*)(outp + (size_t)tok8 * HIDDEN + n0 + cb) = make_float2(y80, y81);
            }
        }
    }
}

// ---------------- launch ----------------
extern "C" void kernel_launch(void* const* d_in, const int* in_sizes, int n_in,
                              void* d_out, int out_size) {
    const float* x      = (const float*)d_in[0];
    const int*   ops    = (const int*)  d_in[1];
    const float* op_emb = (const float*)d_in[2];
    const float* W1     = (const float*)d_in[3];
    const float* b1     = (const float*)d_in[4];
    const float* W2     = (const float*)d_in[5];
    const float* b2     = (const float*)d_in[6];
    float* out = (float*)d_out;

    void *xh = nullptr, *eh = nullptr, *wt1 = nullptr, *wt2 = nullptr;
    cudaGetSymbolAddress(&xh,  g_Xh);
    cudaGetSymbolAddress(&eh,  g_Eh);
    cudaGetSymbolAddress(&wt1, g_WTh1);
    cudaGetSymbolAddress(&wt2, g_WTh2);

    cudaFuncSetAttribute(moe_gemm_h<KAUG, true>,
                         cudaFuncAttributeMaxDynamicSharedMemorySize, SMEM_TOTAL);
    cudaFuncSetAttribute(moe_gemm_h<HIDDEN, false>,
                         cudaFuncAttributeMaxDynamicSharedMemorySize, SMEM_TOTAL);

    zero_counts_kernel<<<1, 32>>>();
    route_kernel<<<BATCH / 256, 256>>>(ops);

    cvt_perm_h_kernel<<<(BATCH * HIDDEN / 8) / 256, 256>>>(x, (__half*)xh, BATCH * HIDDEN / 8);
    cvt_perm_h_kernel<<<(NOPS * EMBD / 8 + 255) / 256, 256>>>(op_emb, (__half*)eh, NOPS * EMBD / 8);

    transpose_h_kernel<<<dim3(HIDDEN/32, KAUG/32, NOPS),   dim3(32, 8)>>>(W1, (__half*)wt1, KAUG, HIDDEN);
    transpose_h_kernel<<<dim3(HIDDEN/32, HIDDEN/32, NOPS), dim3(32, 8)>>>(W2, (__half*)wt2, HIDDEN, HIDDEN);

    dim3 grid(HIDDEN / BN, BATCH / BM, NOPS);
    moe_gemm_h<KAUG,   true ><<<grid, 256, SMEM_TOTAL>>>((const __half*)wt1, b1, out);
    moe_gemm_h<HIDDEN, false><<<grid, 256, SMEM_TOTAL>>>((const __half*)wt2, b2, out);
}

// round 7
// speedup vs baseline: 2.0953x; 1.0710x over previous
#include <cuda_runtime.h>
#include <cuda_fp16.h>
#include <cstdint>

#define HIDDEN 1024
#define EMBD   512
#define NOPS   8
#define BATCH  16384

#define BM 128
#define BN 128
#define BKH 64                      /* halves per k-chunk = 128B rows */
#define NC  (HIDDEN / BKH)          /* 16 k-chunks, both layers */
#define STAGES 3
#define STAGE_BYTES 32768           /* A 16KB + B 16KB */
#define OFF_TOK  (STAGES * STAGE_BYTES)
#define OFF_BIAS (OFF_TOK + 512)
#define OFF_W    (OFF_BIAS + 512)
#define SMEM_TOTAL (OFF_W + 16)

#define MAX_MT 144                  /* max m-tiles: sum ceil(count_e/128) <= 128+8 */

// ---------------- device scratch ----------------
__device__ int    g_counts[NOPS];
__device__ int    g_bucket[NOPS][BATCH];
__device__ int    g_mt_e[MAX_MT];
__device__ int    g_mt_m0[MAX_MT];
__device__ int    g_nmt;
__device__ int    g_ctr[2];
__device__ float  g_C1[NOPS * HIDDEN];                     // folded bias: emb@W1hi + b1
__device__ __half g_Xh[(size_t)BATCH * HIDDEN];            // fp16(x), k-permuted
__device__ __half g_Hh[(size_t)BATCH * HIDDEN];            // fp16(H), k-permuted
__device__ __half g_WTh1[(size_t)NOPS * HIDDEN * HIDDEN];  // [e][n][perm k], k<1024 only
__device__ __half g_WTh2[(size_t)NOPS * HIDDEN * HIDDEN];  // [e][n][perm k]

// ---------------- helpers ----------------
__device__ __forceinline__ uint32_t smem_u32(const void* p) {
    uint32_t a;
    asm("{ .reg .u64 t; cvta.to.shared.u64 t, %1; cvt.u32.u64 %0, t; }" : "=r"(a) : "l"(p));
    return a;
}
__device__ __forceinline__ void cp16(uint32_t dst, const void* src) {
    asm volatile("cp.async.cg.shared.global [%0], [%1], 16;" :: "r"(dst), "l"(src));
}
#define CP_COMMIT() asm volatile("cp.async.commit_group;" ::: "memory")
#define CP_WAIT1()  asm volatile("cp.async.wait_group 1;" ::: "memory")

__device__ __forceinline__ void mma_f16(
    float& c0, float& c1, float& c2, float& c3,
    uint32_t a0, uint32_t a1, uint32_t a2, uint32_t a3,
    uint32_t b0, uint32_t b1)
{
    asm volatile(
        "mma.sync.aligned.m16n8k16.row.col.f32.f16.f16.f32 "
        "{%0,%1,%2,%3}, {%4,%5,%6,%7}, {%8,%9}, {%0,%1,%2,%3};"
        : "+f"(c0), "+f"(c1), "+f"(c2), "+f"(c3)
        : "r"(a0), "r"(a1), "r"(a2), "r"(a3), "r"(b0), "r"(b1));
}

// k-permute within each 64-half block (even k)
__device__ __forceinline__ int hperm(int k) {
    const int s = (k >> 4) & 3, p = (k >> 1) & 7;
    return (k & ~63) + (s >> 1) * 32 + (p & 3) * 8 + (s & 1) * 4 + (p >> 2) * 2;
}

// ---------------- routing + tile table ----------------
__global__ void zero_counts_kernel() {
    if (threadIdx.x < NOPS) g_counts[threadIdx.x] = 0;
    if (threadIdx.x < 2)    g_ctr[threadIdx.x] = 0;
}
__global__ void route_kernel(const int* __restrict__ ops) {
    int t = blockIdx.x * blockDim.x + threadIdx.x;
    if (t < BATCH) {
        int e = ops[t];
        int slot = atomicAdd(&g_counts[e], 1);
        g_bucket[e][slot] = t;
    }
}
__global__ void build_tiles_kernel() {
    if (threadIdx.x == 0) {
        int t = 0;
        for (int e = 0; e < NOPS; e++) {
            const int c = g_counts[e];
            for (int m0 = 0; m0 < c; m0 += BM) {
                g_mt_e[t] = e;
                g_mt_m0[t] = m0;
                t++;
            }
        }
        g_nmt = t;
    }
}

// ---------------- folded bias: c1[e][n] = emb[e] @ W1[e][1024:,:] + b1[e][n] (fp32) ----------------
__global__ void c1_kernel(const float* __restrict__ emb, const float* __restrict__ W1,
                          const float* __restrict__ b1) {
    __shared__ float se[EMBD];
    const int e = blockIdx.y;
    const int n = blockIdx.x * 128 + threadIdx.x;
    #pragma unroll
    for (int i = 0; i < 4; i++) se[threadIdx.x + i * 128] = emb[e * EMBD + threadIdx.x + i * 128];
    __syncthreads();
    float acc = b1[e * HIDDEN + n];
    const float* Wp = W1 + ((size_t)e * (HIDDEN + EMBD) + HIDDEN) * HIDDEN + n;
    #pragma unroll 8
    for (int k = 0; k < EMBD; k++)
        acc = fmaf(se[k], Wp[(size_t)k * HIDDEN], acc);
    g_C1[e * HIDDEN + n] = acc;
}

// ---------------- cvt float -> fp16, k-permuted (x) ----------------
__global__ void cvt_perm_h_kernel(const float* __restrict__ in, __half* __restrict__ out,
                                  int nunits) {
    int t = blockIdx.x * blockDim.x + threadIdx.x;
    if (t >= nunits) return;
    const int blk = t >> 3, u = t & 7;
    const float* src = in + blk * 64;
    __half h[8];
    #pragma unroll
    for (int j = 0; j < 4; j++) {
        const int s = (u >> 2) * 2 + (j >> 1);
        const int p = (u & 3) + (j & 1) * 4;
        const int k = s * 16 + p * 2;
        h[j * 2 + 0] = __float2half_rn(src[k]);
        h[j * 2 + 1] = __float2half_rn(src[k + 1]);
    }
    ((uint4*)out)[t] = *(const uint4*)h;
}

// ---------------- W transpose + fp16 + k-permute: WT[e][n][perm k] = h(W[e][k][n]) ----------------
// source row stride KSRC (k dim of W), dest k-extent KDST (<= KSRC, covers k in [0,KDST))
__global__ void transpose_h_kernel(const float* __restrict__ W, __half* __restrict__ WT,
                                   int KSRC, int KDST, int N) {
    __shared__ float t[32][33];
    const int e = blockIdx.z;
    const float* Wb = W + (size_t)e * KSRC * N;
    __half* WTb = WT + (size_t)e * N * KDST;
    const int k0 = blockIdx.y * 32, n0 = blockIdx.x * 32;
    const int x = threadIdx.x, y = threadIdx.y;   // (32, 8)
    #pragma unroll
    for (int r = 0; r < 4; r++)
        t[y + 8 * r][x] = Wb[(size_t)(k0 + y + 8 * r) * N + n0 + x];
    __syncthreads();
    const int tid = y * 32 + x;
    if (tid < 128) {
        const int n_l = tid >> 2, u2 = tid & 3;
        const int u_abs = ((k0 >> 5) & 1) * 4 + u2;
        __half h[8];
        #pragma unroll
        for (int j = 0; j < 4; j++) {
            const int s = (u_abs >> 2) * 2 + (j >> 1);
            const int p = (u_abs & 3) + (j & 1) * 4;
            const int kl = ((s & 1) * 16 + p * 2);
            h[j * 2 + 0] = __float2half_rn(t[kl][n_l]);
            h[j * 2 + 1] = __float2half_rn(t[kl + 1][n_l]);
        }
        *(uint4*)&WTb[(size_t)(n0 + n_l) * KDST + (k0 & ~63) + u_abs * 8] = *(const uint4*)h;
    }
}

// ---------------- persistent grouped fp16 GEMM via mma.sync m16n8k16 ----------------
// tile 128x128xK1024, 256 threads, 8 warps of 64x32, 3-stage cp.async, 2 CTAs/SM
template<bool IS_L1>
__global__ void __launch_bounds__(256, 2) moe_gemm_h(
    const __half* __restrict__ WT,
    const float* __restrict__ bias,
    float* __restrict__ outp,
    int ctr_idx)
{
    extern __shared__ char smem[];
    const uint32_t sb = smem_u32(smem);
    const int tid = threadIdx.x;
    const int wid = tid >> 5, lane = tid & 31;
    const int g = lane >> 2, t4 = lane & 3;
    const int wm = wid >> 2, wn = wid & 3;     // 2 (m) x 4 (n) warp grid

    int*   sTok  = (int*)(smem + OFF_TOK);
    float* sBias = (float*)(smem + OFF_BIAS);
    int*   sW    = (int*)(smem + OFF_W);

    const __half* __restrict__ Asrc = IS_L1 ? (const __half*)g_Xh : (const __half*)g_Hh;

    const int lu = tid & 7;
    const int lr0 = tid >> 3;
    const uint32_t lsw = (uint32_t)(lu ^ ((lr0 & 1) << 2)) << 4;

    for (;;) {
        __syncthreads();                       // smem reuse guard across tiles
        if (tid == 0) *sW = atomicAdd(&g_ctr[ctr_idx], 1);
        __syncthreads();
        const int w = *sW;
        if (w >= g_nmt * 8) return;

        const int mt = w >> 3;
        const int n0 = (w & 7) * BN;
        const int e  = g_mt_e[mt];
        const int m0 = g_mt_m0[mt];
        const int count = g_counts[e];

        if (tid < 128) {
            int idx = m0 + tid;
            sTok[tid]  = g_bucket[e][idx < count ? idx : count - 1];
            sBias[tid] = bias[e * HIDDEN + n0 + tid];
        }
        __syncthreads();

        const __half* __restrict__ WTe = WT + (size_t)e * HIDDEN * HIDDEN;

        auto load_chunk = [&](int chunk, int buf) {
            const int k0h = chunk * BKH;
            const uint32_t Abu = sb + buf * STAGE_BYTES;
            const uint32_t Bbu = Abu + 16384;
            #pragma unroll
            for (int i = 0; i < 4; i++) {
                const int r = lr0 + i * 32;
                cp16(Abu + r * 128 + lsw, Asrc + (size_t)sTok[r] * HIDDEN + k0h + lu * 8);
                cp16(Bbu + r * 128 + lsw, WTe + (size_t)(n0 + r) * HIDDEN + k0h + lu * 8);
            }
        };

        float c[4][4][4];
        #pragma unroll
        for (int im = 0; im < 4; im++)
            #pragma unroll
            for (int in_ = 0; in_ < 4; in_++)
                #pragma unroll
                for (int j = 0; j < 4; j++) c[im][in_][j] = 0.0f;

        load_chunk(0, 0); CP_COMMIT();
        load_chunk(1, 1); CP_COMMIT();

        for (int i = 0; i < NC; i++) {
            CP_WAIT1();
            __syncthreads();
            const int nb = i + 2;
            if (nb < NC) load_chunk(nb, nb % STAGES);
            CP_COMMIT();

            const char* Ab = smem + (i % STAGES) * STAGE_BYTES;
            const char* Bb = Ab + 16384;

            #pragma unroll
            for (int kb = 0; kb < 2; kb++) {
                uint4 av0[4], av8[4], bv[4];
                #pragma unroll
                for (int im = 0; im < 4; im++) {
                    const int r0 = wm * 64 + im * 16 + g;
                    const int r8 = r0 + 8;
                    av0[im] = *(const uint4*)(Ab + r0 * 128 + (((kb ^ (r0 & 1)) * 4 + t4) << 4));
                    av8[im] = *(const uint4*)(Ab + r8 * 128 + (((kb ^ (r8 & 1)) * 4 + t4) << 4));
                }
                #pragma unroll
                for (int in_ = 0; in_ < 4; in_++) {
                    const int rb = wn * 32 + in_ * 8 + g;
                    bv[in_] = *(const uint4*)(Bb + rb * 128 + (((kb ^ (rb & 1)) * 4 + t4) << 4));
                }
                #pragma unroll
                for (int s2 = 0; s2 < 2; s2++) {
                    #pragma unroll
                    for (int im = 0; im < 4; im++) {
                        const uint32_t a0 = s2 ? av0[im].z : av0[im].x;
                        const uint32_t a2 = s2 ? av0[im].w : av0[im].y;
                        const uint32_t a1 = s2 ? av8[im].z : av8[im].x;
                        const uint32_t a3 = s2 ? av8[im].w : av8[im].y;
                        #pragma unroll
                        for (int in_ = 0; in_ < 4; in_++) {
                            const uint32_t b0 = s2 ? bv[in_].z : bv[in_].x;
                            const uint32_t b1 = s2 ? bv[in_].w : bv[in_].y;
                            mma_f16(c[im][in_][0], c[im][in_][1], c[im][in_][2], c[im][in_][3],
                                    a0, a1, a2, a3, b0, b1);
                        }
                    }
                }
            }
        }

        // ---- epilogue: +bias, relu; L1 -> permuted fp16 H; L2 -> float out ----
        #pragma unroll
        for (int im = 0; im < 4; im++) {
            const int r0 = wm * 64 + im * 16 + g;
            const int r8 = r0 + 8;
            const bool v0 = (m0 + r0) < count;
            const bool v8 = (m0 + r8) < count;
            const int tok0 = sTok[r0];
            const int tok8 = sTok[r8];
            #pragma unroll
            for (int in_ = 0; in_ < 4; in_++) {
                const int cb = wn * 32 + in_ * 8 + 2 * t4;
                const float bias0 = sBias[cb], bias1 = sBias[cb + 1];
                float y00 = fmaxf(c[im][in_][0] + bias0, 0.0f);
                float y01 = fmaxf(c[im][in_][1] + bias1, 0.0f);
                float y80 = fmaxf(c[im][in_][2] + bias0, 0.0f);
                float y81 = fmaxf(c[im][in_][3] + bias1, 0.0f);
                if (IS_L1) {
                    const int ph = hperm(n0 + cb);
                    if (v0) *(__half2*)&g_Hh[(size_t)tok0 * HIDDEN + ph] = __floats2half2_rn(y00, y01);
                    if (v8) *(__half2*)&g_Hh[(size_t)tok8 * HIDDEN + ph] = __floats2half2_rn(y80, y81);
                } else {
                    if (v0) *(float2*)(outp + (size_t)tok0 * HIDDEN + n0 + cb) = make_float2(y00, y01);
                    if (v8) *(float2*)(outp + (size_t)tok8 * HIDDEN + n0 + cb) = make_float2(y80, y81);
                }
            }
        }
    }
}

// ---------------- launch ----------------
extern "C" void kernel_launch(void* const* d_in, const int* in_sizes, int n_in,
                              void* d_out, int out_size) {
    const float* x      = (const float*)d_in[0];
    const int*   ops    = (const int*)  d_in[1];
    const float* op_emb = (const float*)d_in[2];
    const float* W1     = (const float*)d_in[3];
    const float* b1     = (const float*)d_in[4];
    const float* W2     = (const float*)d_in[5];
    const float* b2     = (const float*)d_in[6];
    float* out = (float*)d_out;

    void *xh = nullptr, *wt1 = nullptr, *wt2 = nullptr, *c1 = nullptr;
    cudaGetSymbolAddress(&xh,  g_Xh);
    cudaGetSymbolAddress(&wt1, g_WTh1);
    cudaGetSymbolAddress(&wt2, g_WTh2);
    cudaGetSymbolAddress(&c1,  g_C1);

    cudaFuncSetAttribute(moe_gemm_h<true>,
                         cudaFuncAttributeMaxDynamicSharedMemorySize, SMEM_TOTAL);
    cudaFuncSetAttribute(moe_gemm_h<false>,
                         cudaFuncAttributeMaxDynamicSharedMemorySize, SMEM_TOTAL);

    zero_counts_kernel<<<1, 32>>>();
    route_kernel<<<BATCH / 256, 256>>>(ops);
    build_tiles_kernel<<<1, 32>>>();

    c1_kernel<<<dim3(HIDDEN / 128, NOPS), 128>>>(op_emb, W1, b1);
    cvt_perm_h_kernel<<<(BATCH * HIDDEN / 8) / 256, 256>>>(x, (__half*)xh, BATCH * HIDDEN / 8);

    // W1: only k rows [0,1024) are needed now (emb part folded into c1)
    transpose_h_kernel<<<dim3(HIDDEN/32, HIDDEN/32, NOPS), dim3(32, 8)>>>(W1, (__half*)wt1, HIDDEN + EMBD, HIDDEN, HIDDEN);
    transpose_h_kernel<<<dim3(HIDDEN/32, HIDDEN/32, NOPS), dim3(32, 8)>>>(W2, (__half*)wt2, HIDDEN, HIDDEN, HIDDEN);

    const int nblk = 148 * 2;
    moe_gemm_h<true ><<<nblk, 256, SMEM_TOTAL>>>((const __half*)wt1, (const float*)c1, out, 0);
    moe_gemm_h<false><<<nblk, 256, SMEM_TOTAL>>>((const __half*)wt2, b2, out, 1);
}

// round 8
// speedup vs baseline: 2.3423x; 1.1179x over previous
#include <cuda_runtime.h>
#include <cuda_fp16.h>
#include <cstdint>

#define HIDDEN 1024
#define EMBD   512
#define NOPS   8
#define BATCH  16384

#define BM 128
#define BN 128
#define BKH 64                      /* halves per k-chunk = 128B rows */
#define NC  (HIDDEN / BKH)          /* 16 k-chunks, both layers */
#define STAGES 3
#define STAGE_BYTES 32768           /* A 16KB + B 16KB */
#define OFF_TOK  (STAGES * STAGE_BYTES)
#define OFF_BIAS (OFF_TOK + 512)
#define OFF_W    (OFF_BIAS + 512)
#define SMEM_TOTAL (OFF_W + 16)

#define MAX_MT 144
#define KSPLIT 8

// ---------------- device scratch ----------------
__device__ int    g_counts[NOPS];
__device__ int    g_bucket[NOPS][BATCH];
__device__ int    g_mt_e[MAX_MT];
__device__ int    g_mt_m0[MAX_MT];
__device__ int    g_nmt;
__device__ int    g_ctr[2];
__device__ float  g_C1p[KSPLIT][NOPS * HIDDEN];            // split-k partials
__device__ float  g_C1[NOPS * HIDDEN];                     // folded bias: emb@W1hi + b1
__device__ __half g_Xh[(size_t)BATCH * HIDDEN];            // fp16(x), k-permuted
__device__ __half g_Hh[(size_t)BATCH * HIDDEN];            // fp16(H), k-permuted
__device__ __half g_WTh1[(size_t)NOPS * HIDDEN * HIDDEN];  // [e][n][perm k], k<1024 only
__device__ __half g_WTh2[(size_t)NOPS * HIDDEN * HIDDEN];  // [e][n][perm k]

// ---------------- helpers ----------------
__device__ __forceinline__ uint32_t smem_u32(const void* p) {
    uint32_t a;
    asm("{ .reg .u64 t; cvta.to.shared.u64 t, %1; cvt.u32.u64 %0, t; }" : "=r"(a) : "l"(p));
    return a;
}
__device__ __forceinline__ void cp16(uint32_t dst, const void* src) {
    asm volatile("cp.async.cg.shared.global [%0], [%1], 16;" :: "r"(dst), "l"(src));
}
#define CP_COMMIT() asm volatile("cp.async.commit_group;" ::: "memory")
#define CP_WAIT1()  asm volatile("cp.async.wait_group 1;" ::: "memory")

__device__ __forceinline__ void mma_f16(
    float& c0, float& c1, float& c2, float& c3,
    uint32_t a0, uint32_t a1, uint32_t a2, uint32_t a3,
    uint32_t b0, uint32_t b1)
{
    asm volatile(
        "mma.sync.aligned.m16n8k16.row.col.f32.f16.f16.f32 "
        "{%0,%1,%2,%3}, {%4,%5,%6,%7}, {%8,%9}, {%0,%1,%2,%3};"
        : "+f"(c0), "+f"(c1), "+f"(c2), "+f"(c3)
        : "r"(a0), "r"(a1), "r"(a2), "r"(a3), "r"(b0), "r"(b1));
}

// k-permute within each 64-half block (even k)
__device__ __forceinline__ int hperm(int k) {
    const int s = (k >> 4) & 3, p = (k >> 1) & 7;
    return (k & ~63) + (s >> 1) * 32 + (p & 3) * 8 + (s & 1) * 4 + (p >> 2) * 2;
}

// ---------------- routing + tile table ----------------
__global__ void zero_counts_kernel() {
    if (threadIdx.x < NOPS) g_counts[threadIdx.x] = 0;
    if (threadIdx.x < 2)    g_ctr[threadIdx.x] = 0;
}
__global__ void route_kernel(const int* __restrict__ ops) {
    int t = blockIdx.x * blockDim.x + threadIdx.x;
    if (t < BATCH) {
        int e = ops[t];
        int slot = atomicAdd(&g_counts[e], 1);
        g_bucket[e][slot] = t;
    }
}
__global__ void build_tiles_kernel() {
    if (threadIdx.x == 0) {
        int t = 0;
        for (int e = 0; e < NOPS; e++) {
            const int c = g_counts[e];
            for (int m0 = 0; m0 < c; m0 += BM) {
                g_mt_e[t] = e;
                g_mt_m0[t] = m0;
                t++;
            }
        }
        g_nmt = t;
    }
}

// ---------------- folded bias, split-k ----------------
// partial[ks][e][n] = sum_{k in ks-th 64-slice} emb[e][k] * W1[e][1024+k][n]
__global__ void c1_partial_kernel(const float* __restrict__ emb, const float* __restrict__ W1) {
    __shared__ float se[64];
    const int e  = blockIdx.y;
    const int ks = blockIdx.z * 64;
    const int n  = blockIdx.x * 256 + threadIdx.x;
    if (threadIdx.x < 64) se[threadIdx.x] = emb[e * EMBD + ks + threadIdx.x];
    __syncthreads();
    float acc = 0.0f;
    const float* Wp = W1 + ((size_t)e * (HIDDEN + EMBD) + HIDDEN + ks) * HIDDEN + n;
    #pragma unroll 16
    for (int k = 0; k < 64; k++)
        acc = fmaf(se[k], Wp[(size_t)k * HIDDEN], acc);
    g_C1p[blockIdx.z][e * HIDDEN + n] = acc;
}
// c1 = b1 + sum over splits (fixed order -> deterministic)
__global__ void c1_reduce_kernel(const float* __restrict__ b1) {
    const int i = blockIdx.x * blockDim.x + threadIdx.x;
    float acc = b1[i];
    #pragma unroll
    for (int s = 0; s < KSPLIT; s++) acc += g_C1p[s][i];
    g_C1[i] = acc;
}

// ---------------- cvt float -> fp16, k-permuted (x) ----------------
__global__ void cvt_perm_h_kernel(const float* __restrict__ in, __half* __restrict__ out,
                                  int nunits) {
    int t = blockIdx.x * blockDim.x + threadIdx.x;
    if (t >= nunits) return;
    const int blk = t >> 3, u = t & 7;
    const float* src = in + blk * 64;
    __half h[8];
    #pragma unroll
    for (int j = 0; j < 4; j++) {
        const int s = (u >> 2) * 2 + (j >> 1);
        const int p = (u & 3) + (j & 1) * 4;
        const int k = s * 16 + p * 2;
        h[j * 2 + 0] = __float2half_rn(src[k]);
        h[j * 2 + 1] = __float2half_rn(src[k + 1]);
    }
    ((uint4*)out)[t] = *(const uint4*)h;
}

// ---------------- W transpose + fp16 + k-permute ----------------
__global__ void transpose_h_kernel(const float* __restrict__ W, __half* __restrict__ WT,
                                   int KSRC, int KDST, int N) {
    __shared__ float t[32][33];
    const int e = blockIdx.z;
    const float* Wb = W + (size_t)e * KSRC * N;
    __half* WTb = WT + (size_t)e * N * KDST;
    const int k0 = blockIdx.y * 32, n0 = blockIdx.x * 32;
    const int x = threadIdx.x, y = threadIdx.y;   // (32, 8)
    #pragma unroll
    for (int r = 0; r < 4; r++)
        t[y + 8 * r][x] = Wb[(size_t)(k0 + y + 8 * r) * N + n0 + x];
    __syncthreads();
    const int tid = y * 32 + x;
    if (tid < 128) {
        const int n_l = tid >> 2, u2 = tid & 3;
        const int u_abs = ((k0 >> 5) & 1) * 4 + u2;
        __half h[8];
        #pragma unroll
        for (int j = 0; j < 4; j++) {
            const int s = (u_abs >> 2) * 2 + (j >> 1);
            const int p = (u_abs & 3) + (j & 1) * 4;
            const int kl = ((s & 1) * 16 + p * 2);
            h[j * 2 + 0] = __float2half_rn(t[kl][n_l]);
            h[j * 2 + 1] = __float2half_rn(t[kl + 1][n_l]);
        }
        *(uint4*)&WTb[(size_t)(n0 + n_l) * KDST + (k0 & ~63) + u_abs * 8] = *(const uint4*)h;
    }
}

// ---------------- persistent grouped fp16 GEMM via mma.sync m16n8k16 ----------------
template<bool IS_L1>
__global__ void __launch_bounds__(256, 2) moe_gemm_h(
    const __half* __restrict__ WT,
    const float* __restrict__ bias,
    float* __restrict__ outp,
    int ctr_idx)
{
    extern __shared__ char smem[];
    const uint32_t sb = smem_u32(smem);
    const int tid = threadIdx.x;
    const int wid = tid >> 5, lane = tid & 31;
    const int g = lane >> 2, t4 = lane & 3;
    const int wm = wid >> 2, wn = wid & 3;

    int*   sTok  = (int*)(smem + OFF_TOK);
    float* sBias = (float*)(smem + OFF_BIAS);
    int*   sW    = (int*)(smem + OFF_W);

    const __half* __restrict__ Asrc = IS_L1 ? (const __half*)g_Xh : (const __half*)g_Hh;

    const int lu = tid & 7;
    const int lr0 = tid >> 3;
    const uint32_t lsw = (uint32_t)(lu ^ ((lr0 & 1) << 2)) << 4;

    for (;;) {
        __syncthreads();
        if (tid == 0) *sW = atomicAdd(&g_ctr[ctr_idx], 1);
        __syncthreads();
        const int w = *sW;
        if (w >= g_nmt * 8) return;

        const int mt = w >> 3;
        const int n0 = (w & 7) * BN;
        const int e  = g_mt_e[mt];
        const int m0 = g_mt_m0[mt];
        const int count = g_counts[e];

        if (tid < 128) {
            int idx = m0 + tid;
            sTok[tid]  = g_bucket[e][idx < count ? idx : count - 1];
            sBias[tid] = bias[e * HIDDEN + n0 + tid];
        }
        __syncthreads();

        const __half* __restrict__ WTe = WT + (size_t)e * HIDDEN * HIDDEN;

        auto load_chunk = [&](int chunk, int buf) {
            const int k0h = chunk * BKH;
            const uint32_t Abu = sb + buf * STAGE_BYTES;
            const uint32_t Bbu = Abu + 16384;
            #pragma unroll
            for (int i = 0; i < 4; i++) {
                const int r = lr0 + i * 32;
                cp16(Abu + r * 128 + lsw, Asrc + (size_t)sTok[r] * HIDDEN + k0h + lu * 8);
                cp16(Bbu + r * 128 + lsw, WTe + (size_t)(n0 + r) * HIDDEN + k0h + lu * 8);
            }
        };

        float c[4][4][4];
        #pragma unroll
        for (int im = 0; im < 4; im++)
            #pragma unroll
            for (int in_ = 0; in_ < 4; in_++)
                #pragma unroll
                for (int j = 0; j < 4; j++) c[im][in_][j] = 0.0f;

        load_chunk(0, 0); CP_COMMIT();
        load_chunk(1, 1); CP_COMMIT();

        for (int i = 0; i < NC; i++) {
            CP_WAIT1();
            __syncthreads();
            const int nb = i + 2;
            if (nb < NC) load_chunk(nb, nb % STAGES);
            CP_COMMIT();

            const char* Ab = smem + (i % STAGES) * STAGE_BYTES;
            const char* Bb = Ab + 16384;

            #pragma unroll
            for (int kb = 0; kb < 2; kb++) {
                uint4 av0[4], av8[4], bv[4];
                #pragma unroll
                for (int im = 0; im < 4; im++) {
                    const int r0 = wm * 64 + im * 16 + g;
                    const int r8 = r0 + 8;
                    av0[im] = *(const uint4*)(Ab + r0 * 128 + (((kb ^ (r0 & 1)) * 4 + t4) << 4));
                    av8[im] = *(const uint4*)(Ab + r8 * 128 + (((kb ^ (r8 & 1)) * 4 + t4) << 4));
                }
                #pragma unroll
                for (int in_ = 0; in_ < 4; in_++) {
                    const int rb = wn * 32 + in_ * 8 + g;
                    bv[in_] = *(const uint4*)(Bb + rb * 128 + (((kb ^ (rb & 1)) * 4 + t4) << 4));
                }
                #pragma unroll
                for (int s2 = 0; s2 < 2; s2++) {
                    #pragma unroll
                    for (int im = 0; im < 4; im++) {
                        const uint32_t a0 = s2 ? av0[im].z : av0[im].x;
                        const uint32_t a2 = s2 ? av0[im].w : av0[im].y;
                        const uint32_t a1 = s2 ? av8[im].z : av8[im].x;
                        const uint32_t a3 = s2 ? av8[im].w : av8[im].y;
                        #pragma unroll
                        for (int in_ = 0; in_ < 4; in_++) {
                            const uint32_t b0 = s2 ? bv[in_].z : bv[in_].x;
                            const uint32_t b1 = s2 ? bv[in_].w : bv[in_].y;
                            mma_f16(c[im][in_][0], c[im][in_][1], c[im][in_][2], c[im][in_][3],
                                    a0, a1, a2, a3, b0, b1);
                        }
                    }
                }
            }
        }

        #pragma unroll
        for (int im = 0; im < 4; im++) {
            const int r0 = wm * 64 + im * 16 + g;
            const int r8 = r0 + 8;
            const bool v0 = (m0 + r0) < count;
            const bool v8 = (m0 + r8) < count;
            const int tok0 = sTok[r0];
            const int tok8 = sTok[r8];
            #pragma unroll
            for (int in_ = 0; in_ < 4; in_++) {
                const int cb = wn * 32 + in_ * 8 + 2 * t4;
                const float bias0 = sBias[cb], bias1 = sBias[cb + 1];
                float y00 = fmaxf(c[im][in_][0] + bias0, 0.0f);
                float y01 = fmaxf(c[im][in_][1] + bias1, 0.0f);
                float y80 = fmaxf(c[im][in_][2] + bias0, 0.0f);
                float y81 = fmaxf(c[im][in_][3] + bias1, 0.0f);
                if (IS_L1) {
                    const int ph = hperm(n0 + cb);
                    if (v0) *(__half2*)&g_Hh[(size_t)tok0 * HIDDEN + ph] = __floats2half2_rn(y00, y01);
                    if (v8) *(__half2*)&g_Hh[(size_t)tok8 * HIDDEN + ph] = __floats2half2_rn(y80, y81);
                } else {
                    if (v0) *(float2*)(outp + (size_t)tok0 * HIDDEN + n0 + cb) = make_float2(y00, y01);
                    if (v8) *(float2*)(outp + (size_t)tok8 * HIDDEN + n0 + cb) = make_float2(y80, y81);
                }
            }
        }
    }
}

// ---------------- launch ----------------
extern "C" void kernel_launch(void* const* d_in, const int* in_sizes, int n_in,
                              void* d_out, int out_size) {
    const float* x      = (const float*)d_in[0];
    const int*   ops    = (const int*)  d_in[1];
    const float* op_emb = (const float*)d_in[2];
    const float* W1     = (const float*)d_in[3];
    const float* b1     = (const float*)d_in[4];
    const float* W2     = (const float*)d_in[5];
    const float* b2     = (const float*)d_in[6];
    float* out = (float*)d_out;

    void *xh = nullptr, *wt1 = nullptr, *wt2 = nullptr, *c1 = nullptr;
    cudaGetSymbolAddress(&xh,  g_Xh);
    cudaGetSymbolAddress(&wt1, g_WTh1);
    cudaGetSymbolAddress(&wt2, g_WTh2);
    cudaGetSymbolAddress(&c1,  g_C1);

    cudaFuncSetAttribute(moe_gemm_h<true>,
                         cudaFuncAttributeMaxDynamicSharedMemorySize, SMEM_TOTAL);
    cudaFuncSetAttribute(moe_gemm_h<false>,
                         cudaFuncAttributeMaxDynamicSharedMemorySize, SMEM_TOTAL);

    zero_counts_kernel<<<1, 32>>>();
    route_kernel<<<BATCH / 256, 256>>>(ops);
    build_tiles_kernel<<<1, 32>>>();

    c1_partial_kernel<<<dim3(HIDDEN / 256, NOPS, KSPLIT), 256>>>(op_emb, W1);
    c1_reduce_kernel<<<NOPS * HIDDEN / 256, 256>>>(b1);

    cvt_perm_h_kernel<<<(BATCH * HIDDEN / 8) / 256, 256>>>(x, (__half*)xh, BATCH * HIDDEN / 8);

    transpose_h_kernel<<<dim3(HIDDEN/32, HIDDEN/32, NOPS), dim3(32, 8)>>>(W1, (__half*)wt1, HIDDEN + EMBD, HIDDEN, HIDDEN);
    transpose_h_kernel<<<dim3(HIDDEN/32, HIDDEN/32, NOPS), dim3(32, 8)>>>(W2, (__half*)wt2, HIDDEN, HIDDEN, HIDDEN);

    const int nblk = 148 * 2;
    moe_gemm_h<true ><<<nblk, 256, SMEM_TOTAL>>>((const __half*)wt1, (const float*)c1, out, 0);
    moe_gemm_h<false><<<nblk, 256, SMEM_TOTAL>>>((const __half*)wt2, b2, out, 1);
}